// round 15
// baseline (speedup 1.0000x reference)
#include <cuda_runtime.h>
#include <math.h>

#define BB 64
#define SS 512
#define HH 768
#define LL 9

// ---------------------------------------------------------------------------
// Single fused kernel. Block = (row bi, chunk of 32 compacted slots).
// Re-derives the row scan locally (no scratch, no second kernel).
// ---------------------------------------------------------------------------
__global__ void __launch_bounds__(256, 2) ner_fused_kernel(const float* __restrict__ X,
                                                           const int* __restrict__ mask,
                                                           const float* __restrict__ W,
                                                           const float* __restrict__ bias,
                                                           float* __restrict__ out) {
    const int tid   = threadIdx.x;
    const int lane  = tid & 31;
    const int warp  = tid >> 5;
    const int bi    = blockIdx.x >> 4;     // 16 chunks per row
    const int chunk = blockIdx.x & 15;
    const int c32   = chunk * 32;

    __shared__ float sWt[LL * HH];         // W transposed
    __shared__ int   ssrc[32];             // src token s for this chunk's slots
    __shared__ int   segcnt[16];           // per-32-token-segment popcounts
    __shared__ float sB[LL];

    // ---- local row scan: segment counts via ballots -----------------------
    const int m0 = mask[bi * SS + tid];          // s = tid        (segs 0..7)
    const int m1 = mask[bi * SS + 256 + tid];    // s = 256 + tid  (segs 8..15)
    const unsigned bal0 = __ballot_sync(0xffffffffu, m0 != 0);
    const unsigned bal1 = __ballot_sync(0xffffffffu, m1 != 0);
    if (lane == 0) { segcnt[warp] = __popc(bal0); segcnt[8 + warp] = __popc(bal1); }
    __syncthreads();

    int cnt = 0, ex0 = 0, ex1 = 0;
#pragma unroll
    for (int k = 0; k < 16; k++) {
        const int v = segcnt[k];
        if (k < warp)     ex0 += v;      // exclusive prefix before my m0 segment
        if (k < 8 + warp) ex1 += v;      // exclusive prefix before my m1 segment
        cnt += v;
    }

    // ---- softmax(bias) in registers (cheap, every thread) -----------------
    float tsb[LL];
    {
        float mx = -1e30f;
#pragma unroll
        for (int j = 0; j < LL; j++) { tsb[j] = __ldg(bias + j); mx = fmaxf(mx, tsb[j]); }
        float sum = 0.f;
#pragma unroll
        for (int j = 0; j < LL; j++) { tsb[j] = __expf(tsb[j] - mx); sum += tsb[j]; }
        const float inv = 1.f / sum;
#pragma unroll
        for (int j = 0; j < LL; j++) tsb[j] *= inv;
    }

    if (c32 >= cnt) {                    // dead block: tail fill + exit (uniform)
        float* base = out + ((size_t)bi * SS + c32) * LL;
        for (int i = tid; i < 32 * LL; i += 256) base[i] = tsb[i % LL];
        return;
    }

    // ---- finish scan: publish src indices for this chunk's 32 slots -------
    const unsigned lm = (1u << lane) - 1u;
    if (m0) {
        const int pos = ex0 + __popc(bal0 & lm);
        if (pos >= c32 && pos < c32 + 32) ssrc[pos - c32] = tid;
    }
    if (m1) {
        const int pos = ex1 + __popc(bal1 & lm);
        if (pos >= c32 && pos < c32 + 32) ssrc[pos - c32] = 256 + tid;
    }

    // ---- W transpose: global -> smem (6912 = 27 * 256 exactly) ------------
#pragma unroll 3
    for (int idx = tid; idx < LL * HH; idx += 256) {
        const int k = idx / LL;
        const int j = idx - k * LL;
        sWt[j * HH + k] = W[idx];
    }
    if (tid < LL) sB[tid] = bias[tid];
    __syncthreads();

    // ---- per-warp token work ----------------------------------------------
    const int p0 = c32 + warp * 4;       // first compacted slot of this warp
    const int t0 = bi * SS + p0;         // global slot index
    if (p0 >= cnt) {                     // tail warp in a mixed block
        float* base = out + (size_t)t0 * LL;
        for (int i = lane; i < 4 * LL; i += 32) base[i] = tsb[i % LL];
        return;
    }

    const int nv = min(4, cnt - p0);
    const float4* xp[4];
#pragma unroll
    for (int i = 0; i < 4; i++) {
        const int li = warp * 4 + ((i < nv) ? i : 0);   // clamp to a valid slot
        xp[i] = (const float4*)(X + ((size_t)bi * SS + ssrc[li]) * HH);
    }

    // ---- 3-phase deep-batched mainloop (16 LDG.128 in flight) -------------
    float4 A[4][2], Bf[4][2];
#pragma unroll
    for (int i = 0; i < 4; i++) { A[i][0] = xp[i][lane];      A[i][1] = xp[i][32 + lane]; }
#pragma unroll
    for (int i = 0; i < 4; i++) { Bf[i][0] = xp[i][64 + lane]; Bf[i][1] = xp[i][96 + lane]; }

    float acc[4][LL];
#pragma unroll
    for (int i = 0; i < 4; i++)
#pragma unroll
        for (int j = 0; j < LL; j++) acc[i][j] = 0.f;

#pragma unroll
    for (int h = 0; h < 2; h++) {                       // iters 0,1 (consume A)
        const int k4 = h * 32 + lane;
#pragma unroll
        for (int j = 0; j < LL; j++) {
            const float4 w = *(const float4*)(sWt + j * HH + k4 * 4);
#pragma unroll
            for (int i = 0; i < 4; i++)
                acc[i][j] += A[i][h].x * w.x + A[i][h].y * w.y +
                             A[i][h].z * w.z + A[i][h].w * w.w;
        }
    }
#pragma unroll
    for (int i = 0; i < 4; i++) {                       // reload A: iters 4,5
        A[i][0] = xp[i][128 + lane];
        A[i][1] = xp[i][160 + lane];
    }
#pragma unroll
    for (int h = 0; h < 2; h++) {                       // iters 2,3 (consume Bf)
        const int k4 = (2 + h) * 32 + lane;
#pragma unroll
        for (int j = 0; j < LL; j++) {
            const float4 w = *(const float4*)(sWt + j * HH + k4 * 4);
#pragma unroll
            for (int i = 0; i < 4; i++)
                acc[i][j] += Bf[i][h].x * w.x + Bf[i][h].y * w.y +
                             Bf[i][h].z * w.z + Bf[i][h].w * w.w;
        }
    }
#pragma unroll
    for (int h = 0; h < 2; h++) {                       // iters 4,5 (consume A)
        const int k4 = (4 + h) * 32 + lane;
#pragma unroll
        for (int j = 0; j < LL; j++) {
            const float4 w = *(const float4*)(sWt + j * HH + k4 * 4);
#pragma unroll
            for (int i = 0; i < 4; i++)
                acc[i][j] += A[i][h].x * w.x + A[i][h].y * w.y +
                             A[i][h].z * w.z + A[i][h].w * w.w;
        }
    }

    // ---- warp reduction ----------------------------------------------------
#pragma unroll
    for (int i = 0; i < 4; i++)
#pragma unroll
        for (int j = 0; j < LL; j++) {
            float u = acc[i][j];
            u += __shfl_xor_sync(0xffffffffu, u, 16);
            u += __shfl_xor_sync(0xffffffffu, u, 8);
            u += __shfl_xor_sync(0xffffffffu, u, 4);
            u += __shfl_xor_sync(0xffffffffu, u, 2);
            u += __shfl_xor_sync(0xffffffffu, u, 1);
            acc[i][j] = u;
        }

    // ---- softmax + write ---------------------------------------------------
#pragma unroll
    for (int i = 0; i < 4; i++) {
        if (i < nv) {
            float l[LL];
            float mx = -1e30f;
#pragma unroll
            for (int j = 0; j < LL; j++) { l[j] = acc[i][j] + sB[j]; mx = fmaxf(mx, l[j]); }
            float sum = 0.f;
#pragma unroll
            for (int j = 0; j < LL; j++) { l[j] = __expf(l[j] - mx); sum += l[j]; }
            const float inv = 1.f / sum;
            if (lane < LL) out[(size_t)(t0 + i) * LL + lane] = l[lane] * inv;
        } else {
            if (lane < LL) out[(size_t)(t0 + i) * LL + lane] = tsb[lane];
        }
    }
}

// ---------------------------------------------------------------------------
extern "C" void kernel_launch(void* const* d_in, const int* in_sizes, int n_in,
                              void* d_out, int out_size) {
    const float* seq  = nullptr;  // [64,512,768] f32
    const int*   mask = nullptr;  // [64,512]     i32
    const float* W    = nullptr;  // [768,9]      f32
    const float* bias = nullptr;  // [9]          f32
    for (int i = 0; i < n_in; i++) {
        switch (in_sizes[i]) {
            case BB * SS * HH: seq  = (const float*)d_in[i]; break;
            case BB * SS:      mask = (const int*)d_in[i];   break;
            case HH * LL:      W    = (const float*)d_in[i]; break;
            case LL:           bias = (const float*)d_in[i]; break;
        }
    }
    float* out = (float*)d_out;

    // one self-contained launch: 64 rows x 16 chunks = 1024 blocks
    ner_fused_kernel<<<BB * 16, 256>>>(seq, mask, W, bias, out);
}

// round 16
// speedup vs baseline: 1.1314x; 1.1314x over previous
#include <cuda_runtime.h>
#include <math.h>

#define BB 64
#define SS 512
#define HH 768
#define LL 9

// ---------------------------------------------------------------------------
// Single fused kernel. Block = (row bi, chunk of 32 compacted slots).
// Local ballot scan; W kept in smem in NATIVE [768][9] layout (no transpose):
// each lane's 36 weights for a k4-step are 36 contiguous floats (144B, aligned,
// conflict-free as 9 LDS.128 at 144B lane stride).
// ---------------------------------------------------------------------------
__global__ void __launch_bounds__(256, 2) ner_fused_kernel(const float* __restrict__ X,
                                                           const int* __restrict__ mask,
                                                           const float* __restrict__ W,
                                                           const float* __restrict__ bias,
                                                           float* __restrict__ out) {
    const int tid   = threadIdx.x;
    const int lane  = tid & 31;
    const int warp  = tid >> 5;
    const int bi    = blockIdx.x >> 4;     // 16 chunks per row
    const int chunk = blockIdx.x & 15;
    const int c32   = chunk * 32;

    __shared__ float sW[LL * HH];          // W native layout: sW[k*9 + j]
    __shared__ int   ssrc[32];             // src token s for this chunk's slots
    __shared__ int   segcnt[16];           // per-32-token-segment popcounts
    __shared__ float sB[LL];

    // ---- local row scan: segment counts via ballots -----------------------
    const int m0 = mask[bi * SS + tid];          // s = tid        (segs 0..7)
    const int m1 = mask[bi * SS + 256 + tid];    // s = 256 + tid  (segs 8..15)
    const unsigned bal0 = __ballot_sync(0xffffffffu, m0 != 0);
    const unsigned bal1 = __ballot_sync(0xffffffffu, m1 != 0);
    if (lane == 0) { segcnt[warp] = __popc(bal0); segcnt[8 + warp] = __popc(bal1); }
    __syncthreads();

    int cnt = 0, ex0 = 0, ex1 = 0;
#pragma unroll
    for (int k = 0; k < 16; k++) {
        const int v = segcnt[k];
        if (k < warp)     ex0 += v;
        if (k < 8 + warp) ex1 += v;
        cnt += v;
    }

    // ---- softmax(bias) in registers (cheap, every thread) -----------------
    float tsb[LL];
    {
        float mx = -1e30f;
#pragma unroll
        for (int j = 0; j < LL; j++) { tsb[j] = bias[j]; mx = fmaxf(mx, tsb[j]); }
        float sum = 0.f;
#pragma unroll
        for (int j = 0; j < LL; j++) { tsb[j] = __expf(tsb[j] - mx); sum += tsb[j]; }
        const float inv = 1.f / sum;
#pragma unroll
        for (int j = 0; j < LL; j++) tsb[j] *= inv;
    }

    if (c32 >= cnt) {                    // dead block: tail fill + exit (uniform)
        float* base = out + ((size_t)bi * SS + c32) * LL;
        for (int i = tid; i < 32 * LL; i += 256) base[i] = tsb[i % LL];
        return;
    }

    // ---- finish scan: publish src indices for this chunk's 32 slots -------
    const unsigned lm = (1u << lane) - 1u;
    if (m0) {
        const int pos = ex0 + __popc(bal0 & lm);
        if (pos >= c32 && pos < c32 + 32) ssrc[pos - c32] = tid;
    }
    if (m1) {
        const int pos = ex1 + __popc(bal1 & lm);
        if (pos >= c32 && pos < c32 + 32) ssrc[pos - c32] = 256 + tid;
    }

    // ---- W copy: straight coalesced float4 copy, NO transpose -------------
    {
        const float4* src = (const float4*)W;        // 1728 float4
        float4* dst = (float4*)sW;
        for (int i = tid; i < (LL * HH) / 4; i += 256) dst[i] = src[i];
    }
    if (tid < LL) sB[tid] = bias[tid];
    __syncthreads();

    // ---- per-warp token work ----------------------------------------------
    const int p0 = c32 + warp * 4;       // first compacted slot of this warp
    const int t0 = bi * SS + p0;         // global slot index
    if (p0 >= cnt) {                     // tail warp in a mixed block
        float* base = out + (size_t)t0 * LL;
        for (int i = lane; i < 4 * LL; i += 32) base[i] = tsb[i % LL];
        return;
    }

    const int nv = min(4, cnt - p0);
    const float4* xp[4];
#pragma unroll
    for (int i = 0; i < 4; i++) {
        const int li = warp * 4 + ((i < nv) ? i : 0);   // clamp to a valid slot
        xp[i] = (const float4*)(X + ((size_t)bi * SS + ssrc[li]) * HH);
    }

    float4 c0 = xp[0][lane];
    float4 c1 = xp[1][lane];
    float4 c2 = xp[2][lane];
    float4 c3 = xp[3][lane];

    float acc[4][LL];
#pragma unroll
    for (int i = 0; i < 4; i++)
#pragma unroll
        for (int j = 0; j < LL; j++) acc[i][j] = 0.f;

#pragma unroll
    for (int it = 0; it < HH / 128; it++) {   // 6 iterations, 16B x-load/lane
        const int k4 = it * 32 + lane;        // this lane's k4 chunk (k = 4*k4..)
        float4 n0, n1, n2, n3;
        if (it < HH / 128 - 1) {              // prefetch next iteration's x
            const int kn = k4 + 32;
            n0 = xp[0][kn]; n1 = xp[1][kn]; n2 = xp[2][kn]; n3 = xp[3][kn];
        }

        // 36 contiguous weights for k = 4*k4 .. 4*k4+3 (native layout)
        const float4* wb = (const float4*)(sW + k4 * 36);
        float wf[36];
#pragma unroll
        for (int c = 0; c < 9; c++) {
            const float4 t = wb[c];
            wf[4 * c]     = t.x;
            wf[4 * c + 1] = t.y;
            wf[4 * c + 2] = t.z;
            wf[4 * c + 3] = t.w;
        }

#pragma unroll
        for (int j = 0; j < LL; j++) {
            // wf[j + 9*c] = W[4*k4 + c][j]
            acc[0][j] += c0.x * wf[j] + c0.y * wf[j + 9] + c0.z * wf[j + 18] + c0.w * wf[j + 27];
            acc[1][j] += c1.x * wf[j] + c1.y * wf[j + 9] + c1.z * wf[j + 18] + c1.w * wf[j + 27];
            acc[2][j] += c2.x * wf[j] + c2.y * wf[j + 9] + c2.z * wf[j + 18] + c2.w * wf[j + 27];
            acc[3][j] += c3.x * wf[j] + c3.y * wf[j + 9] + c3.z * wf[j + 18] + c3.w * wf[j + 27];
        }
        if (it < HH / 128 - 1) { c0 = n0; c1 = n1; c2 = n2; c3 = n3; }
    }

    // ---- warp reduction ----------------------------------------------------
#pragma unroll
    for (int i = 0; i < 4; i++)
#pragma unroll
        for (int j = 0; j < LL; j++) {
            float u = acc[i][j];
            u += __shfl_xor_sync(0xffffffffu, u, 16);
            u += __shfl_xor_sync(0xffffffffu, u, 8);
            u += __shfl_xor_sync(0xffffffffu, u, 4);
            u += __shfl_xor_sync(0xffffffffu, u, 2);
            u += __shfl_xor_sync(0xffffffffu, u, 1);
            acc[i][j] = u;
        }

    // ---- softmax + write ---------------------------------------------------
#pragma unroll
    for (int i = 0; i < 4; i++) {
        if (i < nv) {
            float l[LL];
            float mx = -1e30f;
#pragma unroll
            for (int j = 0; j < LL; j++) { l[j] = acc[i][j] + sB[j]; mx = fmaxf(mx, l[j]); }
            float sum = 0.f;
#pragma unroll
            for (int j = 0; j < LL; j++) { l[j] = __expf(l[j] - mx); sum += l[j]; }
            const float inv = 1.f / sum;
            if (lane < LL) out[(size_t)(t0 + i) * LL + lane] = l[lane] * inv;
        } else {
            if (lane < LL) out[(size_t)(t0 + i) * LL + lane] = tsb[lane];
        }
    }
}

// ---------------------------------------------------------------------------
extern "C" void kernel_launch(void* const* d_in, const int* in_sizes, int n_in,
                              void* d_out, int out_size) {
    const float* seq  = nullptr;  // [64,512,768] f32
    const int*   mask = nullptr;  // [64,512]     i32
    const float* W    = nullptr;  // [768,9]      f32
    const float* bias = nullptr;  // [9]          f32
    for (int i = 0; i < n_in; i++) {
        switch (in_sizes[i]) {
            case BB * SS * HH: seq  = (const float*)d_in[i]; break;
            case BB * SS:      mask = (const int*)d_in[i];   break;
            case HH * LL:      W    = (const float*)d_in[i]; break;
            case LL:           bias = (const float*)d_in[i]; break;
        }
    }
    float* out = (float*)d_out;

    // one self-contained launch: 64 rows x 16 chunks = 1024 blocks
    ner_fused_kernel<<<BB * 16, 256>>>(seq, mask, W, bias, out);
}